// round 15
// baseline (speedup 1.0000x reference)
#include <cuda_runtime.h>
#include <cuda_bf16.h>
#include <cuda_fp16.h>
#include <math.h>

typedef unsigned int uint;

#define C_DIM   768
#define NCLS    200
#define BATCH   16
#define M_ROWS  (BATCH * 784)   // 12544
#define NPAD    224
#define FF_ELEMS (BATCH * 64 * 768)
#define IMG_OUT_ELEMS (BATCH * 3 * 224 * 224)

// ---------------- scratch (device globals; no runtime alloc allowed) -------
__device__ float g_maxprob[M_ROWS];
__device__ int   g_sel[BATCH];
__device__ __align__(16) __half g_Wfch[NPAD * C_DIM];     // fc W fp16
__device__ __align__(16) __half g_Wph[768 * C_DIM];       // parts W fp16 (hi)
__device__ __align__(16) float g_bias[768];
__device__ __align__(16) __half g_Ah[3][1024 * C_DIM];    // A fp16 hi
__device__ __align__(16) __half g_Al[3][1024 * C_DIM];    // A fp16 lo

__device__ __forceinline__ uint h2u(__half2 v) {
    return *reinterpret_cast<uint*>(&v);
}
__device__ __forceinline__ uint smem_u32(const void* p) {
    return (uint)__cvta_generic_to_shared(p);
}
// fp16 split
__device__ __forceinline__ void split4h(float4 v, uint2& hv, uint2& lv) {
    __half2 h01 = __floats2half2_rn(v.x, v.y);
    __half2 h23 = __floats2half2_rn(v.z, v.w);
    float2 f01 = __half22float2(h01), f23 = __half22float2(h23);
    hv = make_uint2(h2u(h01), h2u(h23));
    lv = make_uint2(h2u(__floats2half2_rn(v.x - f01.x, v.y - f01.y)),
                    h2u(__floats2half2_rn(v.z - f23.x, v.w - f23.y)));
}
// fp16 convert (hi only)
__device__ __forceinline__ uint2 cvt4h(float4 v) {
    return make_uint2(h2u(__floats2half2_rn(v.x, v.y)),
                      h2u(__floats2half2_rn(v.z, v.w)));
}

#define MMA_F16(c0,c1,c2,c3,a0,a1,a2,a3,b0,b1)                               \
    asm volatile("mma.sync.aligned.m16n8k16.row.col.f32.f16.f16.f32 "        \
        "{%0,%1,%2,%3}, {%4,%5,%6,%7}, {%8,%9}, {%0,%1,%2,%3};"              \
        : "+f"(c0), "+f"(c1), "+f"(c2), "+f"(c3)                             \
        : "r"(a0), "r"(a1), "r"(a2), "r"(a3), "r"(b0), "r"(b1))

#define LDSM_X4(r0,r1,r2,r3,addr)                                            \
    asm volatile("ldmatrix.sync.aligned.m8n8.x4.shared.b16 {%0,%1,%2,%3}, [%4];" \
        : "=r"(r0), "=r"(r1), "=r"(r2), "=r"(r3) : "r"(addr))

#define CP_ASYNC16(dst, src) \
    asm volatile("cp.async.cg.shared.global [%0], [%1], 16;" :: "r"(dst), "l"(src))
#define CP_COMMIT() asm volatile("cp.async.commit_group;")
#define CP_WAIT0()  asm volatile("cp.async.wait_group 0;")

// ===========================================================================
// Kernel 0: weight conversion + bias concat.  fc + parts -> fp16 hi only.
// ===========================================================================
#define FC4 (NPAD * C_DIM / 4)    // 43008
#define P4  (768 * C_DIM / 4)     // 147456

__global__ void conv_w_kernel(const float* __restrict__ Wfc,
                              const float* __restrict__ Wl,
                              const float* __restrict__ Wm,
                              const float* __restrict__ Ws,
                              const float* __restrict__ bl,
                              const float* __restrict__ bm,
                              const float* __restrict__ bsv)
{
    int idx = blockIdx.x * blockDim.x + threadIdx.x;
    if (idx < FC4) {
        int row = idx / 192, kq = idx % 192;
        float4 v = (row < NCLS) ? *(const float4*)&Wfc[(size_t)row * C_DIM + kq * 4]
                                : make_float4(0.f, 0.f, 0.f, 0.f);
        *(uint2*)&g_Wfch[idx * 4] = cvt4h(v);
    } else if (idx < FC4 + P4) {
        int j = idx - FC4;
        int row = j / 192, kq = j % 192;
        const float* src = (row < 192) ? &Wl[(size_t)row * C_DIM]
                         : (row < 384) ? &Wm[(size_t)(row - 192) * C_DIM]
                                       : &Ws[(size_t)(row - 384) * C_DIM];
        float4 v = *(const float4*)&src[kq * 4];
        *(uint2*)&g_Wph[j * 4] = cvt4h(v);
    }
    if (idx < 768)
        g_bias[idx] = (idx < 192) ? bl[idx]
                    : (idx < 384) ? bm[idx - 192] : bsv[idx - 384];
}

// ===========================================================================
// Kernel 1: fc GEMM (plain fp16 HMMA, 1 chain) + fused softmax reduce.
// CTA = 64 rows x 224 cols, 128 thr = 4 warps (m32 x n112).
// ===========================================================================
#define FC_ST      40
#define FC_XBUF_B  (64 * FC_ST * 2)        // 5120 B
#define FC_WBUF_B  (224 * FC_ST * 2)       // 17920 B
#define W_IT_B     (32 * FC_ST * 2)        // 2560 B
#define FC_SMEM    (2 * FC_XBUF_B + 2 * FC_WBUF_B + 1024)   // 47104

__global__ __launch_bounds__(128, 2)
void fc_mma_kernel(const float* __restrict__ x, const float* __restrict__ bfc)
{
    extern __shared__ __align__(16) char sm_raw[];
    __half* sxh = (__half*)sm_raw;
    __half* swh = (__half*)(sm_raw + 2 * FC_XBUF_B);
    float* red = (float*)(sm_raw + 2 * FC_XBUF_B + 2 * FC_WBUF_B);

    const int tid = threadIdx.x, lane = tid & 31, warp = tid >> 5;
    const int g = lane >> 2, t = lane & 3;
    const int wm = warp & 1, wn = warp >> 1;
    const int m0 = blockIdx.x * 64;

    const int xrow = tid >> 1, xq = tid & 1;
    const float4* xp = (const float4*)(x + (size_t)(m0 + xrow) * C_DIM);
    char* sxh_dst = (char*)(sxh + xrow * FC_ST + xq * 16);

    const int wrow = tid >> 2, wq = tid & 3;
    const __half* whsrc = g_Wfch + (size_t)wrow * C_DIM + wq * 8;
    const uint wdh = smem_u32(swh + wrow * FC_ST + wq * 8);

    uint ah_addr[2];
#pragma unroll
    for (int i = 0; i < 2; i++) {
        uint ab = (uint)((wm * 32 + i * 16 + (lane & 15)) * FC_ST + (lane >> 4) * 8) * 2;
        ah_addr[i] = smem_u32(sxh) + ab;
    }
    const uint b_base  = (uint)((wn * 112 + ((lane >> 4) & 1) * 8 + (lane & 7)) * FC_ST
                                + ((lane >> 3) & 1) * 8) * 2;
    const uint bh_addr = smem_u32(swh) + b_base;

    float acc[2][14][4];
#pragma unroll
    for (int i = 0; i < 2; i++)
#pragma unroll
        for (int j = 0; j < 14; j++)
#pragma unroll
            for (int q = 0; q < 4; q++) acc[i][j][q] = 0.f;

    float4 xr[4];
#pragma unroll
    for (int i = 0; i < 4; i++) xr[i] = xp[xq * 4 + i];
#pragma unroll
    for (int it = 0; it < 7; it++)
        CP_ASYNC16(wdh + it * W_IT_B, whsrc + (size_t)it * 32 * C_DIM);
    CP_COMMIT();
#pragma unroll
    for (int i = 0; i < 4; i++)
        *(uint2*)(sxh_dst + i * 8) = cvt4h(xr[i]);
    CP_WAIT0();
    __syncthreads();

    for (int step = 0; step < 24; step++) {
        const int buf = step & 1;
        const uint xoff  = (uint)buf * FC_XBUF_B;
        const uint woff  = (uint)buf * FC_WBUF_B;
        const uint nxoff = (uint)(buf ^ 1) * FC_XBUF_B;
        const uint nwoff = (uint)(buf ^ 1) * FC_WBUF_B;

        if (step < 23) {
            const int k4 = (step + 1) * 8 + xq * 4;
#pragma unroll
            for (int i = 0; i < 4; i++) xr[i] = xp[k4 + i];
            const int ke = (step + 1) * 32;
#pragma unroll
            for (int it = 0; it < 7; it++)
                CP_ASYNC16(wdh + nwoff + it * W_IT_B, whsrc + (size_t)it * 32 * C_DIM + ke);
            CP_COMMIT();
        }

#pragma unroll
        for (int c = 0; c < 2; c++) {
            const uint coff = c * 32;
            uint ah[2][4];
#pragma unroll
            for (int i = 0; i < 2; i++)
                LDSM_X4(ah[i][0], ah[i][1], ah[i][2], ah[i][3], ah_addr[i] + xoff + coff);
#pragma unroll
            for (int jp = 0; jp < 7; jp++) {
                uint bh[4];
                LDSM_X4(bh[0], bh[1], bh[2], bh[3], bh_addr + woff + jp * 1280 + coff);
                const int j0 = 2 * jp, j1 = j0 + 1;
#pragma unroll
                for (int i = 0; i < 2; i++) {
                    MMA_F16(acc[i][j0][0], acc[i][j0][1], acc[i][j0][2], acc[i][j0][3],
                            ah[i][0], ah[i][1], ah[i][2], ah[i][3], bh[0], bh[1]);
                    MMA_F16(acc[i][j1][0], acc[i][j1][1], acc[i][j1][2], acc[i][j1][3],
                            ah[i][0], ah[i][1], ah[i][2], ah[i][3], bh[2], bh[3]);
                }
            }
        }

        if (step < 23) {
#pragma unroll
            for (int i = 0; i < 4; i++)
                *(uint2*)(sxh_dst + nxoff + i * 8) = cvt4h(xr[i]);
            CP_WAIT0();
        }
        __syncthreads();
    }

    // ---- epilogue: bias + mask, fused row max / sumexp reduce ----
#pragma unroll
    for (int j = 0; j < 14; j++) {
        int col = wn * 112 + j * 8 + t * 2;
        float b0 = (col < NCLS) ? bfc[col] : 0.f;
        float b1 = (col + 1 < NCLS) ? bfc[col + 1] : 0.f;
#pragma unroll
        for (int i = 0; i < 2; i++) {
            if (col < NCLS) { acc[i][j][0] += b0; acc[i][j][2] += b0; }
            else            { acc[i][j][0] = acc[i][j][2] = -1e30f; }
            if (col + 1 < NCLS) { acc[i][j][1] += b1; acc[i][j][3] += b1; }
            else                { acc[i][j][1] = acc[i][j][3] = -1e30f; }
        }
    }
#pragma unroll
    for (int i = 0; i < 2; i++) {
        const int r0 = wm * 32 + i * 16 + g, r1 = r0 + 8;
        float mx0 = -1e30f, mx1 = -1e30f;
#pragma unroll
        for (int j = 0; j < 14; j++) {
            mx0 = fmaxf(mx0, fmaxf(acc[i][j][0], acc[i][j][1]));
            mx1 = fmaxf(mx1, fmaxf(acc[i][j][2], acc[i][j][3]));
        }
#pragma unroll
        for (int off = 1; off <= 2; off <<= 1) {
            mx0 = fmaxf(mx0, __shfl_xor_sync(0xffffffffu, mx0, off));
            mx1 = fmaxf(mx1, __shfl_xor_sync(0xffffffffu, mx1, off));
        }
        if (t == 0) { red[wn * 64 + r0] = mx0; red[wn * 64 + r1] = mx1; }
    }
    __syncthreads();
#pragma unroll
    for (int i = 0; i < 2; i++) {
        const int r0 = wm * 32 + i * 16 + g, r1 = r0 + 8;
        const float rm0 = fmaxf(red[r0], red[64 + r0]);
        const float rm1 = fmaxf(red[r1], red[64 + r1]);
        float s0 = 0.f, s1 = 0.f;
#pragma unroll
        for (int j = 0; j < 14; j++) {
            s0 += expf(acc[i][j][0] - rm0) + expf(acc[i][j][1] - rm0);
            s1 += expf(acc[i][j][2] - rm1) + expf(acc[i][j][3] - rm1);
        }
#pragma unroll
        for (int off = 1; off <= 2; off <<= 1) {
            s0 += __shfl_xor_sync(0xffffffffu, s0, off);
            s1 += __shfl_xor_sync(0xffffffffu, s1, off);
        }
        if (t == 0) { red[128 + wn * 64 + r0] = s0; red[128 + wn * 64 + r1] = s1; }
    }
    __syncthreads();
    if (wn == 0 && t == 0) {
#pragma unroll
        for (int i = 0; i < 2; i++) {
            const int r0 = wm * 32 + i * 16 + g, r1 = r0 + 8;
            g_maxprob[m0 + r0] = 1.f / (red[128 + r0] + red[128 + 64 + r0]);
            g_maxprob[m0 + r1] = 1.f / (red[128 + r1] + red[128 + 64 + r1]);
        }
    }
}

// ===========================================================================
// Kernel 2: part_logits (8x8 mean-pool, stride 3, pad 2) * mask -> argmax
// ===========================================================================
__global__ void sel_kernel(const float* __restrict__ mask)
{
    int b = blockIdx.x;
    __shared__ float map[784];
    __shared__ float vals[81];
    int p = threadIdx.x;
    for (int i = p; i < 784; i += 128) map[i] = g_maxprob[b * 784 + i];
    __syncthreads();
    if (p < 81) {
        int oy = p / 9, ox = p % 9;
        float s = 0.f;
#pragma unroll
        for (int i = 0; i < 8; i++) {
            int h = oy * 3 - 2 + i;
            if (h < 0 || h >= 28) continue;
#pragma unroll
            for (int j = 0; j < 8; j++) {
                int w = ox * 3 - 2 + j;
                if (w < 0 || w >= 28) continue;
                s += map[h * 28 + w];
            }
        }
        vals[p] = mask[b * 81 + p] * (s * (1.f / 64.f));
    }
    __syncthreads();
    if (p == 0) {
        float best = vals[0];
        int bi = 0;
        for (int q = 1; q < 81; q++)
            if (vals[q] > best) { best = vals[q]; bi = q; }
        g_sel[b] = bi;
    }
}

// ===========================================================================
// Kernel 3: gather selected patches -> fp16 hi/lo A matrices (x4 vectorized)
// ===========================================================================
__global__ void gather_kernel(const float* __restrict__ x)
{
    int p    = blockIdx.x;
    int b    = blockIdx.y;
    int part = blockIdx.z;
    int sel  = g_sel[b];
    int oy = sel / 9, ox = sel % 9;
    int i = p >> 3, j = p & 7;
    int c = threadIdx.x * 4;

    const float* xb = x + (size_t)b * 784 * C_DIM;
    __half* oh = &g_Ah[part][(size_t)(b * 64 + p) * C_DIM + c];
    __half* ol = &g_Al[part][(size_t)(b * 64 + p) * C_DIM + c];

    float4 v;
    if (part == 0) {
        int h = oy * 3 - 2 + i, w = ox * 3 - 2 + j;
        bool ok = (h >= 0 && h < 28 && w >= 0 && w < 28);
        v = ok ? *(const float4*)&xb[(size_t)(h * 28 + w) * C_DIM + c]
               : make_float4(0.f, 0.f, 0.f, 0.f);
    } else {
        int   n, basepad;
        float scale, offs;
        if (part == 1) { n = 6; basepad = 1; scale = 0.75f; offs = -0.125f; }
        else           { n = 4; basepad = 0; scale = 0.5f;  offs = -0.25f;  }
        float sy = fminf(fmaxf(scale * i + offs, 0.f), (float)(n - 1));
        float sx = fminf(fmaxf(scale * j + offs, 0.f), (float)(n - 1));
        int iy0 = (int)sy; float fy = sy - iy0; int iy1 = min(iy0 + 1, n - 1);
        int ix0 = (int)sx; float fx = sx - ix0; int ix1 = min(ix0 + 1, n - 1);
        int hb = oy * 3 - basepad, wb = ox * 3 - basepad;
        int h0 = hb + iy0, h1 = hb + iy1, w0 = wb + ix0, w1 = wb + ix1;
        bool okh0 = (h0 >= 0 && h0 < 28), okh1 = (h1 >= 0 && h1 < 28);
        bool okw0 = (w0 >= 0 && w0 < 28), okw1 = (w1 >= 0 && w1 < 28);
        bool ok00 = okh0 && okw0, ok01 = okh0 && okw1;
        bool ok10 = okh1 && okw0, ok11 = okh1 && okw1;
        const float4 z = make_float4(0.f, 0.f, 0.f, 0.f);
        float4 v00 = ok00 ? *(const float4*)&xb[(size_t)(h0 * 28 + w0) * C_DIM + c] : z;
        float4 v01 = ok01 ? *(const float4*)&xb[(size_t)(h0 * 28 + w1) * C_DIM + c] : z;
        float4 v10 = ok10 ? *(const float4*)&xb[(size_t)(h1 * 28 + w0) * C_DIM + c] : z;
        float4 v11 = ok11 ? *(const float4*)&xb[(size_t)(h1 * 28 + w1) * C_DIM + c] : z;
        float gy = 1.f - fy, gx = 1.f - fx;
        v.x = gy * (gx * v00.x + fx * v01.x) + fy * (gx * v10.x + fx * v11.x);
        v.y = gy * (gx * v00.y + fx * v01.y) + fy * (gx * v10.y + fx * v11.y);
        v.z = gy * (gx * v00.z + fx * v01.z) + fy * (gx * v10.z + fx * v11.z);
        v.w = gy * (gx * v00.w + fx * v01.w) + fy * (gx * v10.w + fx * v11.w);
    }
    uint2 hv, lv; split4h(v, hv, lv);
    *(uint2*)oh = hv;
    *(uint2*)ol = lv;
}

// ===========================================================================
// Kernel 4: parts GEMM (fp16 2-chain: xh*wh + xl*wh). BM=64, BN=64, BK=32.
// grid(16,12), 256 thr.
// ===========================================================================
#define P_ST    40
#define P_BUF   (64 * P_ST)
#define P_BUF_B (P_BUF * 2)

__global__ __launch_bounds__(256, 3)
void parts_mma_kernel(float* __restrict__ out)
{
    __shared__ __align__(16) __half sah[2][P_BUF], sal[2][P_BUF];
    __shared__ __align__(16) __half swh[2][P_BUF];

    const int tid = threadIdx.x, lane = tid & 31, warp = tid >> 5;
    const int g = lane >> 2, t = lane & 3;
    const int wm = warp & 3, wn = warp >> 2;
    const int m0 = blockIdx.x * 64;
    const int n0c = blockIdx.y * 64;
    const int part = (n0c < 192) ? 0 : (n0c < 384) ? 1 : 2;

    // fill: 3 chunks per thread (A hi, A lo, W hi); row = tid>>2, q = tid&3
    const int frow = tid >> 2, fq = tid & 3;
    const __half* ahsrc = g_Ah[part] + (size_t)(m0 + frow) * C_DIM + fq * 8;
    const __half* alsrc = g_Al[part] + (size_t)(m0 + frow) * C_DIM + fq * 8;
    const __half* whsrc = g_Wph + (size_t)(n0c + frow) * C_DIM + fq * 8;
    const uint ahdst = smem_u32(sah[0] + frow * P_ST + fq * 8);
    const uint aldst = smem_u32(sal[0] + frow * P_ST + fq * 8);
    const uint whdst = smem_u32(swh[0] + frow * P_ST + fq * 8);

    const uint a_base  = (uint)((wm * 16 + (lane & 15)) * P_ST + (lane >> 4) * 8) * 2;
    const uint ah_addr = smem_u32(sah[0]) + a_base;
    const uint al_addr = smem_u32(sal[0]) + a_base;
    const uint b_base  = (uint)((wn * 32 + ((lane >> 4) & 1) * 8 + (lane & 7)) * P_ST
                                + ((lane >> 3) & 1) * 8) * 2;
    const uint bh_addr = smem_u32(swh[0]) + b_base;

    float acc[4][4];
#pragma unroll
    for (int j = 0; j < 4; j++)
#pragma unroll
        for (int q = 0; q < 4; q++) acc[j][q] = 0.f;

    CP_ASYNC16(ahdst, ahsrc);
    CP_ASYNC16(aldst, alsrc);
    CP_ASYNC16(whdst, whsrc);
    CP_COMMIT();
    CP_WAIT0();
    __syncthreads();

    for (int step = 0; step < 24; step++) {
        const int buf = step & 1;
        const uint off  = (uint)buf * P_BUF_B;
        const uint noff = (uint)(buf ^ 1) * P_BUF_B;

        if (step < 23) {
            CP_ASYNC16(ahdst + noff, ahsrc + (step + 1) * 32);
            CP_ASYNC16(aldst + noff, alsrc + (step + 1) * 32);
            CP_ASYNC16(whdst + noff, whsrc + (step + 1) * 32);
            CP_COMMIT();
        }

#pragma unroll
        for (int c = 0; c < 2; c++) {
            const uint coff = c * 32;
            uint ah[4], al[4];
            LDSM_X4(ah[0], ah[1], ah[2], ah[3], ah_addr + off + coff);
            LDSM_X4(al[0], al[1], al[2], al[3], al_addr + off + coff);
#pragma unroll
            for (int jp = 0; jp < 2; jp++) {
                uint bh[4];
                LDSM_X4(bh[0], bh[1], bh[2], bh[3], bh_addr + off + jp * 1280 + coff);
                const int j0 = 2 * jp, j1 = j0 + 1;
                MMA_F16(acc[j0][0], acc[j0][1], acc[j0][2], acc[j0][3],
                        ah[0], ah[1], ah[2], ah[3], bh[0], bh[1]);
                MMA_F16(acc[j0][0], acc[j0][1], acc[j0][2], acc[j0][3],
                        al[0], al[1], al[2], al[3], bh[0], bh[1]);
                MMA_F16(acc[j1][0], acc[j1][1], acc[j1][2], acc[j1][3],
                        ah[0], ah[1], ah[2], ah[3], bh[2], bh[3]);
                MMA_F16(acc[j1][0], acc[j1][1], acc[j1][2], acc[j1][3],
                        al[0], al[1], al[2], al[3], bh[2], bh[3]);
            }
        }

        if (step < 23) CP_WAIT0();
        __syncthreads();
    }

#pragma unroll
    for (int j = 0; j < 4; j++) {
        int col = n0c + wn * 32 + j * 8 + t * 2;
        int m   = m0 + wm * 16 + g;
        float2 bc = *(float2*)&g_bias[col];
        *(float2*)&out[(size_t)m * 768 + col] =
            make_float2(acc[j][0] + bc.x, acc[j][1] + bc.y);
        *(float2*)&out[(size_t)(m + 8) * 768 + col] =
            make_float2(acc[j][2] + bc.x, acc[j][3] + bc.y);
    }
}

// ===========================================================================
// Kernel 5: image patch gather + bilinear 224.  grid (48, 28), 224 thr.
// ===========================================================================
__global__ void image_kernel(const float* __restrict__ img, float* __restrict__ out)
{
    int bc = blockIdx.x;
    int b  = bc / 3;
    int ox = threadIdx.x;

    int sel = g_sel[b];
    int r0 = (sel / 9) * 48 - 32;
    int c0 = (sel % 9) * 48 - 32;

    const float s = 128.f / 224.f;
    float sx = fminf(fmaxf((ox + 0.5f) * s - 0.5f, 0.f), 127.f);
    int px0 = (int)sx; float fx = sx - px0; int px1 = min(px0 + 1, 127);
    int gx0 = c0 + px0, gx1 = c0 + px1;
    bool okx0 = (gx0 >= 0 && gx0 < 448), okx1 = (gx1 >= 0 && gx1 < 448);

    const float* ib = img + (size_t)bc * 448 * 448;
    float* ob = out + (size_t)bc * 224 * 224;

#pragma unroll
    for (int oy8 = 0; oy8 < 8; oy8++) {
        int oy = blockIdx.y * 8 + oy8;
        float sy = fminf(fmaxf((oy + 0.5f) * s - 0.5f, 0.f), 127.f);
        int py0 = (int)sy; float fy = sy - py0; int py1 = min(py0 + 1, 127);
        int gy0 = r0 + py0, gy1 = r0 + py1;
        bool oky0 = (gy0 >= 0 && gy0 < 448), oky1 = (gy1 >= 0 && gy1 < 448);
        float v00 = (oky0 && okx0) ? ib[gy0 * 448 + gx0] : 0.f;
        float v01 = (oky0 && okx1) ? ib[gy0 * 448 + gx1] : 0.f;
        float v10 = (oky1 && okx0) ? ib[gy1 * 448 + gx0] : 0.f;
        float v11 = (oky1 && okx1) ? ib[gy1 * 448 + gx1] : 0.f;
        ob[oy * 224 + ox] = (1.f - fy) * ((1.f - fx) * v00 + fx * v01)
                          +        fy  * ((1.f - fx) * v10 + fx * v11);
    }
}

// ===========================================================================
extern "C" void kernel_launch(void* const* d_in, const int* in_sizes, int n_in,
                              void* d_out, int out_size)
{
    const float* x    = (const float*)d_in[0];
    const float* mask = (const float*)d_in[1];
    const float* img  = (const float*)d_in[2];
    const float* Wfc  = (const float*)d_in[3];
    const float* bfc  = (const float*)d_in[4];
    const float* Wl   = (const float*)d_in[5];
    const float* bl   = (const float*)d_in[6];
    const float* Wm   = (const float*)d_in[7];
    const float* bm   = (const float*)d_in[8];
    const float* Ws   = (const float*)d_in[9];
    const float* bsv  = (const float*)d_in[10];

    float* out_ff  = (float*)d_out;
    float* out_img = (float*)d_out + FF_ELEMS;

    conv_w_kernel<<<(FC4 + P4 + 255) / 256, 256>>>(Wfc, Wl, Wm, Ws, bl, bm, bsv);

    cudaFuncSetAttribute(fc_mma_kernel,
                         cudaFuncAttributeMaxDynamicSharedMemorySize, FC_SMEM);
    fc_mma_kernel<<<M_ROWS / 64, 128, FC_SMEM>>>(x, bfc);

    sel_kernel<<<BATCH, 128>>>(mask);
    {
        dim3 g(64, BATCH, 3);
        gather_kernel<<<g, 192>>>(x);
    }
    {
        dim3 g(16, 12);
        parts_mma_kernel<<<g, 256>>>(out_ff);
    }
    {
        dim3 g(48, 28);
        image_kernel<<<g, 224>>>(img, out_img);
    }
}

// round 16
// speedup vs baseline: 1.4319x; 1.4319x over previous
#include <cuda_runtime.h>
#include <cuda_bf16.h>
#include <cuda_fp16.h>
#include <math.h>

typedef unsigned int uint;

#define C_DIM   768
#define NCLS    200
#define BATCH   16
#define M_ROWS  (BATCH * 784)   // 12544
#define NPAD    224
#define FF_ELEMS (BATCH * 64 * 768)
#define IMG_OUT_ELEMS (BATCH * 3 * 224 * 224)

// ---------------- scratch (device globals; no runtime alloc allowed) -------
__device__ float g_maxprob[M_ROWS];
__device__ int   g_sel[BATCH];
__device__ __align__(16) __half g_Wfch[NPAD * C_DIM];     // fc W fp16
__device__ __align__(16) __half g_Wph[768 * C_DIM];       // parts W fp16 (hi)
__device__ __align__(16) float g_bias[768];
__device__ __align__(16) __half g_Ah[3][1024 * C_DIM];    // A fp16 hi
__device__ __align__(16) __half g_Al[3][1024 * C_DIM];    // A fp16 lo

__device__ __forceinline__ uint h2u(__half2 v) {
    return *reinterpret_cast<uint*>(&v);
}
__device__ __forceinline__ uint smem_u32(const void* p) {
    return (uint)__cvta_generic_to_shared(p);
}
// fp16 split
__device__ __forceinline__ void split4h(float4 v, uint2& hv, uint2& lv) {
    __half2 h01 = __floats2half2_rn(v.x, v.y);
    __half2 h23 = __floats2half2_rn(v.z, v.w);
    float2 f01 = __half22float2(h01), f23 = __half22float2(h23);
    hv = make_uint2(h2u(h01), h2u(h23));
    lv = make_uint2(h2u(__floats2half2_rn(v.x - f01.x, v.y - f01.y)),
                    h2u(__floats2half2_rn(v.z - f23.x, v.w - f23.y)));
}
// fp16 convert (hi only)
__device__ __forceinline__ uint2 cvt4h(float4 v) {
    return make_uint2(h2u(__floats2half2_rn(v.x, v.y)),
                      h2u(__floats2half2_rn(v.z, v.w)));
}

#define MMA_F16(c0,c1,c2,c3,a0,a1,a2,a3,b0,b1)                               \
    asm volatile("mma.sync.aligned.m16n8k16.row.col.f32.f16.f16.f32 "        \
        "{%0,%1,%2,%3}, {%4,%5,%6,%7}, {%8,%9}, {%0,%1,%2,%3};"              \
        : "+f"(c0), "+f"(c1), "+f"(c2), "+f"(c3)                             \
        : "r"(a0), "r"(a1), "r"(a2), "r"(a3), "r"(b0), "r"(b1))

#define LDSM_X4(r0,r1,r2,r3,addr)                                            \
    asm volatile("ldmatrix.sync.aligned.m8n8.x4.shared.b16 {%0,%1,%2,%3}, [%4];" \
        : "=r"(r0), "=r"(r1), "=r"(r2), "=r"(r3) : "r"(addr))

#define CP_ASYNC16(dst, src) \
    asm volatile("cp.async.cg.shared.global [%0], [%1], 16;" :: "r"(dst), "l"(src))
#define CP_COMMIT() asm volatile("cp.async.commit_group;")
#define CP_WAIT0()  asm volatile("cp.async.wait_group 0;")

// ===========================================================================
// Kernel 0: weight conversion + bias concat.  fc + parts -> fp16 hi only.
// ===========================================================================
#define FC4 (NPAD * C_DIM / 4)    // 43008
#define P4  (768 * C_DIM / 4)     // 147456

__global__ void conv_w_kernel(const float* __restrict__ Wfc,
                              const float* __restrict__ Wl,
                              const float* __restrict__ Wm,
                              const float* __restrict__ Ws,
                              const float* __restrict__ bl,
                              const float* __restrict__ bm,
                              const float* __restrict__ bsv)
{
    int idx = blockIdx.x * blockDim.x + threadIdx.x;
    if (idx < FC4) {
        int row = idx / 192, kq = idx % 192;
        float4 v = (row < NCLS) ? *(const float4*)&Wfc[(size_t)row * C_DIM + kq * 4]
                                : make_float4(0.f, 0.f, 0.f, 0.f);
        *(uint2*)&g_Wfch[idx * 4] = cvt4h(v);
    } else if (idx < FC4 + P4) {
        int j = idx - FC4;
        int row = j / 192, kq = j % 192;
        const float* src = (row < 192) ? &Wl[(size_t)row * C_DIM]
                         : (row < 384) ? &Wm[(size_t)(row - 192) * C_DIM]
                                       : &Ws[(size_t)(row - 384) * C_DIM];
        float4 v = *(const float4*)&src[kq * 4];
        *(uint2*)&g_Wph[j * 4] = cvt4h(v);
    }
    if (idx < 768)
        g_bias[idx] = (idx < 192) ? bl[idx]
                    : (idx < 384) ? bm[idx - 192] : bsv[idx - 384];
}

// ===========================================================================
// Kernel 1: fc GEMM (plain fp16 HMMA, 1 chain) + fused softmax reduce.
// CTA = 64 rows x 224 cols, 128 thr = 4 warps (m32 x n112).
// ===========================================================================
#define FC_ST      40
#define FC_XBUF_B  (64 * FC_ST * 2)        // 5120 B
#define FC_WBUF_B  (224 * FC_ST * 2)       // 17920 B
#define W_IT_B     (32 * FC_ST * 2)        // 2560 B
#define FC_SMEM    (2 * FC_XBUF_B + 2 * FC_WBUF_B + 1024)   // 47104

__global__ __launch_bounds__(128, 2)
void fc_mma_kernel(const float* __restrict__ x, const float* __restrict__ bfc)
{
    extern __shared__ __align__(16) char sm_raw[];
    __half* sxh = (__half*)sm_raw;
    __half* swh = (__half*)(sm_raw + 2 * FC_XBUF_B);
    float* red = (float*)(sm_raw + 2 * FC_XBUF_B + 2 * FC_WBUF_B);

    const int tid = threadIdx.x, lane = tid & 31, warp = tid >> 5;
    const int g = lane >> 2, t = lane & 3;
    const int wm = warp & 1, wn = warp >> 1;
    const int m0 = blockIdx.x * 64;

    const int xrow = tid >> 1, xq = tid & 1;
    const float4* xp = (const float4*)(x + (size_t)(m0 + xrow) * C_DIM);
    char* sxh_dst = (char*)(sxh + xrow * FC_ST + xq * 16);

    const int wrow = tid >> 2, wq = tid & 3;
    const __half* whsrc = g_Wfch + (size_t)wrow * C_DIM + wq * 8;
    const uint wdh = smem_u32(swh + wrow * FC_ST + wq * 8);

    uint ah_addr[2];
#pragma unroll
    for (int i = 0; i < 2; i++) {
        uint ab = (uint)((wm * 32 + i * 16 + (lane & 15)) * FC_ST + (lane >> 4) * 8) * 2;
        ah_addr[i] = smem_u32(sxh) + ab;
    }
    const uint b_base  = (uint)((wn * 112 + ((lane >> 4) & 1) * 8 + (lane & 7)) * FC_ST
                                + ((lane >> 3) & 1) * 8) * 2;
    const uint bh_addr = smem_u32(swh) + b_base;

    float acc[2][14][4];
#pragma unroll
    for (int i = 0; i < 2; i++)
#pragma unroll
        for (int j = 0; j < 14; j++)
#pragma unroll
            for (int q = 0; q < 4; q++) acc[i][j][q] = 0.f;

    float4 xr[4];
#pragma unroll
    for (int i = 0; i < 4; i++) xr[i] = xp[xq * 4 + i];
#pragma unroll
    for (int it = 0; it < 7; it++)
        CP_ASYNC16(wdh + it * W_IT_B, whsrc + (size_t)it * 32 * C_DIM);
    CP_COMMIT();
#pragma unroll
    for (int i = 0; i < 4; i++)
        *(uint2*)(sxh_dst + i * 8) = cvt4h(xr[i]);
    CP_WAIT0();
    __syncthreads();

    for (int step = 0; step < 24; step++) {
        const int buf = step & 1;
        const uint xoff  = (uint)buf * FC_XBUF_B;
        const uint woff  = (uint)buf * FC_WBUF_B;
        const uint nxoff = (uint)(buf ^ 1) * FC_XBUF_B;
        const uint nwoff = (uint)(buf ^ 1) * FC_WBUF_B;

        if (step < 23) {
            const int k4 = (step + 1) * 8 + xq * 4;
#pragma unroll
            for (int i = 0; i < 4; i++) xr[i] = xp[k4 + i];
            const int ke = (step + 1) * 32;
#pragma unroll
            for (int it = 0; it < 7; it++)
                CP_ASYNC16(wdh + nwoff + it * W_IT_B, whsrc + (size_t)it * 32 * C_DIM + ke);
            CP_COMMIT();
        }

#pragma unroll
        for (int c = 0; c < 2; c++) {
            const uint coff = c * 32;
            uint ah[2][4];
#pragma unroll
            for (int i = 0; i < 2; i++)
                LDSM_X4(ah[i][0], ah[i][1], ah[i][2], ah[i][3], ah_addr[i] + xoff + coff);
#pragma unroll
            for (int jp = 0; jp < 7; jp++) {
                uint bh[4];
                LDSM_X4(bh[0], bh[1], bh[2], bh[3], bh_addr + woff + jp * 1280 + coff);
                const int j0 = 2 * jp, j1 = j0 + 1;
#pragma unroll
                for (int i = 0; i < 2; i++) {
                    MMA_F16(acc[i][j0][0], acc[i][j0][1], acc[i][j0][2], acc[i][j0][3],
                            ah[i][0], ah[i][1], ah[i][2], ah[i][3], bh[0], bh[1]);
                    MMA_F16(acc[i][j1][0], acc[i][j1][1], acc[i][j1][2], acc[i][j1][3],
                            ah[i][0], ah[i][1], ah[i][2], ah[i][3], bh[2], bh[3]);
                }
            }
        }

        if (step < 23) {
#pragma unroll
            for (int i = 0; i < 4; i++)
                *(uint2*)(sxh_dst + nxoff + i * 8) = cvt4h(xr[i]);
            CP_WAIT0();
        }
        __syncthreads();
    }

    // ---- epilogue: bias + mask, fused row max / sumexp reduce ----
#pragma unroll
    for (int j = 0; j < 14; j++) {
        int col = wn * 112 + j * 8 + t * 2;
        float b0 = (col < NCLS) ? bfc[col] : 0.f;
        float b1 = (col + 1 < NCLS) ? bfc[col + 1] : 0.f;
#pragma unroll
        for (int i = 0; i < 2; i++) {
            if (col < NCLS) { acc[i][j][0] += b0; acc[i][j][2] += b0; }
            else            { acc[i][j][0] = acc[i][j][2] = -1e30f; }
            if (col + 1 < NCLS) { acc[i][j][1] += b1; acc[i][j][3] += b1; }
            else                { acc[i][j][1] = acc[i][j][3] = -1e30f; }
        }
    }
#pragma unroll
    for (int i = 0; i < 2; i++) {
        const int r0 = wm * 32 + i * 16 + g, r1 = r0 + 8;
        float mx0 = -1e30f, mx1 = -1e30f;
#pragma unroll
        for (int j = 0; j < 14; j++) {
            mx0 = fmaxf(mx0, fmaxf(acc[i][j][0], acc[i][j][1]));
            mx1 = fmaxf(mx1, fmaxf(acc[i][j][2], acc[i][j][3]));
        }
#pragma unroll
        for (int off = 1; off <= 2; off <<= 1) {
            mx0 = fmaxf(mx0, __shfl_xor_sync(0xffffffffu, mx0, off));
            mx1 = fmaxf(mx1, __shfl_xor_sync(0xffffffffu, mx1, off));
        }
        if (t == 0) { red[wn * 64 + r0] = mx0; red[wn * 64 + r1] = mx1; }
    }
    __syncthreads();
#pragma unroll
    for (int i = 0; i < 2; i++) {
        const int r0 = wm * 32 + i * 16 + g, r1 = r0 + 8;
        const float rm0 = fmaxf(red[r0], red[64 + r0]);
        const float rm1 = fmaxf(red[r1], red[64 + r1]);
        float s0 = 0.f, s1 = 0.f;
#pragma unroll
        for (int j = 0; j < 14; j++) {
            s0 += expf(acc[i][j][0] - rm0) + expf(acc[i][j][1] - rm0);
            s1 += expf(acc[i][j][2] - rm1) + expf(acc[i][j][3] - rm1);
        }
#pragma unroll
        for (int off = 1; off <= 2; off <<= 1) {
            s0 += __shfl_xor_sync(0xffffffffu, s0, off);
            s1 += __shfl_xor_sync(0xffffffffu, s1, off);
        }
        if (t == 0) { red[128 + wn * 64 + r0] = s0; red[128 + wn * 64 + r1] = s1; }
    }
    __syncthreads();
    if (wn == 0 && t == 0) {
#pragma unroll
        for (int i = 0; i < 2; i++) {
            const int r0 = wm * 32 + i * 16 + g, r1 = r0 + 8;
            g_maxprob[m0 + r0] = 1.f / (red[128 + r0] + red[128 + 64 + r0]);
            g_maxprob[m0 + r1] = 1.f / (red[128 + r1] + red[128 + 64 + r1]);
        }
    }
}

// ===========================================================================
// Kernel 2: part_logits (8x8 mean-pool, stride 3, pad 2) * mask -> argmax
// ===========================================================================
__global__ void sel_kernel(const float* __restrict__ mask)
{
    int b = blockIdx.x;
    __shared__ float map[784];
    __shared__ float vals[81];
    int p = threadIdx.x;
    for (int i = p; i < 784; i += 128) map[i] = g_maxprob[b * 784 + i];
    __syncthreads();
    if (p < 81) {
        int oy = p / 9, ox = p % 9;
        float s = 0.f;
#pragma unroll
        for (int i = 0; i < 8; i++) {
            int h = oy * 3 - 2 + i;
            if (h < 0 || h >= 28) continue;
#pragma unroll
            for (int j = 0; j < 8; j++) {
                int w = ox * 3 - 2 + j;
                if (w < 0 || w >= 28) continue;
                s += map[h * 28 + w];
            }
        }
        vals[p] = mask[b * 81 + p] * (s * (1.f / 64.f));
    }
    __syncthreads();
    if (p == 0) {
        float best = vals[0];
        int bi = 0;
        for (int q = 1; q < 81; q++)
            if (vals[q] > best) { best = vals[q]; bi = q; }
        g_sel[b] = bi;
    }
}

// ===========================================================================
// Kernel 3: gather selected patches -> fp16 hi/lo A matrices (x4 vectorized)
// ===========================================================================
__global__ void gather_kernel(const float* __restrict__ x)
{
    int p    = blockIdx.x;
    int b    = blockIdx.y;
    int part = blockIdx.z;
    int sel  = __ldg(&g_sel[b]);
    int oy = sel / 9, ox = sel % 9;
    int i = p >> 3, j = p & 7;
    int c = threadIdx.x * 4;

    const float* xb = x + (size_t)b * 784 * C_DIM;
    __half* oh = &g_Ah[part][(size_t)(b * 64 + p) * C_DIM + c];
    __half* ol = &g_Al[part][(size_t)(b * 64 + p) * C_DIM + c];

    float4 v;
    if (part == 0) {
        int h = oy * 3 - 2 + i, w = ox * 3 - 2 + j;
        bool ok = (h >= 0 && h < 28 && w >= 0 && w < 28);
        v = ok ? *(const float4*)&xb[(size_t)(h * 28 + w) * C_DIM + c]
               : make_float4(0.f, 0.f, 0.f, 0.f);
    } else {
        int   n, basepad;
        float scale, offs;
        if (part == 1) { n = 6; basepad = 1; scale = 0.75f; offs = -0.125f; }
        else           { n = 4; basepad = 0; scale = 0.5f;  offs = -0.25f;  }
        float sy = fminf(fmaxf(scale * i + offs, 0.f), (float)(n - 1));
        float sx = fminf(fmaxf(scale * j + offs, 0.f), (float)(n - 1));
        int iy0 = (int)sy; float fy = sy - iy0; int iy1 = min(iy0 + 1, n - 1);
        int ix0 = (int)sx; float fx = sx - ix0; int ix1 = min(ix0 + 1, n - 1);
        int hb = oy * 3 - basepad, wb = ox * 3 - basepad;
        int h0 = hb + iy0, h1 = hb + iy1, w0 = wb + ix0, w1 = wb + ix1;
        bool okh0 = (h0 >= 0 && h0 < 28), okh1 = (h1 >= 0 && h1 < 28);
        bool okw0 = (w0 >= 0 && w0 < 28), okw1 = (w1 >= 0 && w1 < 28);
        bool ok00 = okh0 && okw0, ok01 = okh0 && okw1;
        bool ok10 = okh1 && okw0, ok11 = okh1 && okw1;
        const float4 z = make_float4(0.f, 0.f, 0.f, 0.f);
        float4 v00 = ok00 ? *(const float4*)&xb[(size_t)(h0 * 28 + w0) * C_DIM + c] : z;
        float4 v01 = ok01 ? *(const float4*)&xb[(size_t)(h0 * 28 + w1) * C_DIM + c] : z;
        float4 v10 = ok10 ? *(const float4*)&xb[(size_t)(h1 * 28 + w0) * C_DIM + c] : z;
        float4 v11 = ok11 ? *(const float4*)&xb[(size_t)(h1 * 28 + w1) * C_DIM + c] : z;
        float gy = 1.f - fy, gx = 1.f - fx;
        v.x = gy * (gx * v00.x + fx * v01.x) + fy * (gx * v10.x + fx * v11.x);
        v.y = gy * (gx * v00.y + fx * v01.y) + fy * (gx * v10.y + fx * v11.y);
        v.z = gy * (gx * v00.z + fx * v01.z) + fy * (gx * v10.z + fx * v11.z);
        v.w = gy * (gx * v00.w + fx * v01.w) + fy * (gx * v10.w + fx * v11.w);
    }
    uint2 hv, lv; split4h(v, hv, lv);
    *(uint2*)oh = hv;
    *(uint2*)ol = lv;
}

// ===========================================================================
// Kernel 4: parts GEMM (fp16 2-chain: xh*wh + xl*wh). BM=64, BN=64, BK=32.
// grid(16,12), 256 thr.
// ===========================================================================
#define P_ST    40
#define P_BUF   (64 * P_ST)
#define P_BUF_B (P_BUF * 2)

__global__ __launch_bounds__(256, 3)
void parts_mma_kernel(float* __restrict__ out)
{
    __shared__ __align__(16) __half sah[2][P_BUF], sal[2][P_BUF];
    __shared__ __align__(16) __half swh[2][P_BUF];

    const int tid = threadIdx.x, lane = tid & 31, warp = tid >> 5;
    const int g = lane >> 2, t = lane & 3;
    const int wm = warp & 3, wn = warp >> 2;
    const int m0 = blockIdx.x * 64;
    const int n0c = blockIdx.y * 64;
    const int part = (n0c < 192) ? 0 : (n0c < 384) ? 1 : 2;

    const int frow = tid >> 2, fq = tid & 3;
    const __half* ahsrc = g_Ah[part] + (size_t)(m0 + frow) * C_DIM + fq * 8;
    const __half* alsrc = g_Al[part] + (size_t)(m0 + frow) * C_DIM + fq * 8;
    const __half* whsrc = g_Wph + (size_t)(n0c + frow) * C_DIM + fq * 8;
    const uint ahdst = smem_u32(sah[0] + frow * P_ST + fq * 8);
    const uint aldst = smem_u32(sal[0] + frow * P_ST + fq * 8);
    const uint whdst = smem_u32(swh[0] + frow * P_ST + fq * 8);

    const uint a_base  = (uint)((wm * 16 + (lane & 15)) * P_ST + (lane >> 4) * 8) * 2;
    const uint ah_addr = smem_u32(sah[0]) + a_base;
    const uint al_addr = smem_u32(sal[0]) + a_base;
    const uint b_base  = (uint)((wn * 32 + ((lane >> 4) & 1) * 8 + (lane & 7)) * P_ST
                                + ((lane >> 3) & 1) * 8) * 2;
    const uint bh_addr = smem_u32(swh[0]) + b_base;

    float acc[4][4];
#pragma unroll
    for (int j = 0; j < 4; j++)
#pragma unroll
        for (int q = 0; q < 4; q++) acc[j][q] = 0.f;

    CP_ASYNC16(ahdst, ahsrc);
    CP_ASYNC16(aldst, alsrc);
    CP_ASYNC16(whdst, whsrc);
    CP_COMMIT();
    CP_WAIT0();
    __syncthreads();

    for (int step = 0; step < 24; step++) {
        const int buf = step & 1;
        const uint off  = (uint)buf * P_BUF_B;
        const uint noff = (uint)(buf ^ 1) * P_BUF_B;

        if (step < 23) {
            CP_ASYNC16(ahdst + noff, ahsrc + (step + 1) * 32);
            CP_ASYNC16(aldst + noff, alsrc + (step + 1) * 32);
            CP_ASYNC16(whdst + noff, whsrc + (step + 1) * 32);
            CP_COMMIT();
        }

#pragma unroll
        for (int c = 0; c < 2; c++) {
            const uint coff = c * 32;
            uint ah[4], al[4];
            LDSM_X4(ah[0], ah[1], ah[2], ah[3], ah_addr + off + coff);
            LDSM_X4(al[0], al[1], al[2], al[3], al_addr + off + coff);
#pragma unroll
            for (int jp = 0; jp < 2; jp++) {
                uint bh[4];
                LDSM_X4(bh[0], bh[1], bh[2], bh[3], bh_addr + off + jp * 1280 + coff);
                const int j0 = 2 * jp, j1 = j0 + 1;
                MMA_F16(acc[j0][0], acc[j0][1], acc[j0][2], acc[j0][3],
                        ah[0], ah[1], ah[2], ah[3], bh[0], bh[1]);
                MMA_F16(acc[j0][0], acc[j0][1], acc[j0][2], acc[j0][3],
                        al[0], al[1], al[2], al[3], bh[0], bh[1]);
                MMA_F16(acc[j1][0], acc[j1][1], acc[j1][2], acc[j1][3],
                        ah[0], ah[1], ah[2], ah[3], bh[2], bh[3]);
                MMA_F16(acc[j1][0], acc[j1][1], acc[j1][2], acc[j1][3],
                        al[0], al[1], al[2], al[3], bh[2], bh[3]);
            }
        }

        if (step < 23) CP_WAIT0();
        __syncthreads();
    }

#pragma unroll
    for (int j = 0; j < 4; j++) {
        int col = n0c + wn * 32 + j * 8 + t * 2;
        int m   = m0 + wm * 16 + g;
        float2 bc = *(float2*)&g_bias[col];
        *(float2*)&out[(size_t)m * 768 + col] =
            make_float2(acc[j][0] + bc.x, acc[j][1] + bc.y);
        *(float2*)&out[(size_t)(m + 8) * 768 + col] =
            make_float2(acc[j][2] + bc.x, acc[j][3] + bc.y);
    }
}

// ===========================================================================
// Kernel 5: image patch gather + bilinear 224.  grid (48, 28), 224 thr.
// ===========================================================================
__global__ void image_kernel(const float* __restrict__ img, float* __restrict__ out)
{
    int bc = blockIdx.x;
    int b  = bc / 3;
    int ox = threadIdx.x;

    int sel = __ldg(&g_sel[b]);
    int r0 = (sel / 9) * 48 - 32;
    int c0 = (sel % 9) * 48 - 32;

    const float s = 128.f / 224.f;
    float sx = fminf(fmaxf((ox + 0.5f) * s - 0.5f, 0.f), 127.f);
    int px0 = (int)sx; float fx = sx - px0; int px1 = min(px0 + 1, 127);
    int gx0 = c0 + px0, gx1 = c0 + px1;
    bool okx0 = (gx0 >= 0 && gx0 < 448), okx1 = (gx1 >= 0 && gx1 < 448);

    const float* ib = img + (size_t)bc * 448 * 448;
    float* ob = out + (size_t)bc * 224 * 224;

#pragma unroll
    for (int oy8 = 0; oy8 < 8; oy8++) {
        int oy = blockIdx.y * 8 + oy8;
        float sy = fminf(fmaxf((oy + 0.5f) * s - 0.5f, 0.f), 127.f);
        int py0 = (int)sy; float fy = sy - py0; int py1 = min(py0 + 1, 127);
        int gy0 = r0 + py0, gy1 = r0 + py1;
        bool oky0 = (gy0 >= 0 && gy0 < 448), oky1 = (gy1 >= 0 && gy1 < 448);
        float v00 = (oky0 && okx0) ? ib[gy0 * 448 + gx0] : 0.f;
        float v01 = (oky0 && okx1) ? ib[gy0 * 448 + gx1] : 0.f;
        float v10 = (oky1 && okx0) ? ib[gy1 * 448 + gx0] : 0.f;
        float v11 = (oky1 && okx1) ? ib[gy1 * 448 + gx1] : 0.f;
        ob[oy * 224 + ox] = (1.f - fy) * ((1.f - fx) * v00 + fx * v01)
                          +        fy  * ((1.f - fx) * v10 + fx * v11);
    }
}

// ===========================================================================
extern "C" void kernel_launch(void* const* d_in, const int* in_sizes, int n_in,
                              void* d_out, int out_size)
{
    const float* x    = (const float*)d_in[0];
    const float* mask = (const float*)d_in[1];
    const float* img  = (const float*)d_in[2];
    const float* Wfc  = (const float*)d_in[3];
    const float* bfc  = (const float*)d_in[4];
    const float* Wl   = (const float*)d_in[5];
    const float* bl   = (const float*)d_in[6];
    const float* Wm   = (const float*)d_in[7];
    const float* bm   = (const float*)d_in[8];
    const float* Ws   = (const float*)d_in[9];
    const float* bsv  = (const float*)d_in[10];

    float* out_ff  = (float*)d_out;
    float* out_img = (float*)d_out + FF_ELEMS;

    conv_w_kernel<<<(FC4 + P4 + 255) / 256, 256>>>(Wfc, Wl, Wm, Ws, bl, bm, bsv);

    cudaFuncSetAttribute(fc_mma_kernel,
                         cudaFuncAttributeMaxDynamicSharedMemorySize, FC_SMEM);
    fc_mma_kernel<<<M_ROWS / 64, 128, FC_SMEM>>>(x, bfc);

    sel_kernel<<<BATCH, 128>>>(mask);
    {
        dim3 g(64, BATCH, 3);
        gather_kernel<<<g, 192>>>(x);
    }
    {
        dim3 g(16, 12);
        parts_mma_kernel<<<g, 256>>>(out_ff);
    }
    {
        dim3 g(48, 28);
        image_kernel<<<g, 224>>>(img, out_img);
    }
}

// round 17
// speedup vs baseline: 1.5262x; 1.0658x over previous
#include <cuda_runtime.h>
#include <cuda_fp16.h>
#include <math.h>

typedef unsigned int uint;

#define C_DIM   768
#define NCLS    200
#define BATCH   16
#define M_ROWS  (BATCH * 784)   // 12544
#define NPAD    224
#define FF_ELEMS (BATCH * 64 * 768)
#define IMG_OUT_ELEMS (BATCH * 3 * 224 * 224)

// ---------------- scratch (device globals; no runtime alloc allowed) -------
__device__ float g_maxprob[M_ROWS];
__device__ int   g_sel[BATCH];
__device__ __align__(16) __half g_Wfch[NPAD * C_DIM];     // fc W fp16
__device__ __align__(16) __half g_Wph[768 * C_DIM];       // parts W fp16
__device__ __align__(16) float g_bias[768];
__device__ __align__(16) __half g_Ah[3][1024 * C_DIM];    // A fp16

__device__ __forceinline__ uint h2u(__half2 v) {
    return *reinterpret_cast<uint*>(&v);
}
__device__ __forceinline__ uint smem_u32(const void* p) {
    return (uint)__cvta_generic_to_shared(p);
}
// fp16 convert
__device__ __forceinline__ uint2 cvt4h(float4 v) {
    return make_uint2(h2u(__floats2half2_rn(v.x, v.y)),
                      h2u(__floats2half2_rn(v.z, v.w)));
}

#define MMA_F16(c0,c1,c2,c3,a0,a1,a2,a3,b0,b1)                               \
    asm volatile("mma.sync.aligned.m16n8k16.row.col.f32.f16.f16.f32 "        \
        "{%0,%1,%2,%3}, {%4,%5,%6,%7}, {%8,%9}, {%0,%1,%2,%3};"              \
        : "+f"(c0), "+f"(c1), "+f"(c2), "+f"(c3)                             \
        : "r"(a0), "r"(a1), "r"(a2), "r"(a3), "r"(b0), "r"(b1))

#define LDSM_X4(r0,r1,r2,r3,addr)                                            \
    asm volatile("ldmatrix.sync.aligned.m8n8.x4.shared.b16 {%0,%1,%2,%3}, [%4];" \
        : "=r"(r0), "=r"(r1), "=r"(r2), "=r"(r3) : "r"(addr))

#define CP_ASYNC16(dst, src) \
    asm volatile("cp.async.cg.shared.global [%0], [%1], 16;" :: "r"(dst), "l"(src))
#define CP_COMMIT() asm volatile("cp.async.commit_group;")
#define CP_WAIT0()  asm volatile("cp.async.wait_group 0;")

// ===========================================================================
// Kernel 0: weight conversion + bias concat.  All weights -> fp16.
// ===========================================================================
#define FC4 (NPAD * C_DIM / 4)    // 43008
#define P4  (768 * C_DIM / 4)     // 147456

__global__ void conv_w_kernel(const float* __restrict__ Wfc,
                              const float* __restrict__ Wl,
                              const float* __restrict__ Wm,
                              const float* __restrict__ Ws,
                              const float* __restrict__ bl,
                              const float* __restrict__ bm,
                              const float* __restrict__ bsv)
{
    int idx = blockIdx.x * blockDim.x + threadIdx.x;
    if (idx < FC4) {
        int row = idx / 192, kq = idx % 192;
        float4 v = (row < NCLS) ? *(const float4*)&Wfc[(size_t)row * C_DIM + kq * 4]
                                : make_float4(0.f, 0.f, 0.f, 0.f);
        *(uint2*)&g_Wfch[idx * 4] = cvt4h(v);
    } else if (idx < FC4 + P4) {
        int j = idx - FC4;
        int row = j / 192, kq = j % 192;
        const float* src = (row < 192) ? &Wl[(size_t)row * C_DIM]
                         : (row < 384) ? &Wm[(size_t)(row - 192) * C_DIM]
                                       : &Ws[(size_t)(row - 384) * C_DIM];
        float4 v = *(const float4*)&src[kq * 4];
        *(uint2*)&g_Wph[j * 4] = cvt4h(v);
    }
    if (idx < 768)
        g_bias[idx] = (idx < 192) ? bl[idx]
                    : (idx < 384) ? bm[idx - 192] : bsv[idx - 384];
}

// ===========================================================================
// Kernel 1: fc GEMM (plain fp16 HMMA) + fused softmax reduce.
// CTA = 64 rows x 224 cols, 128 thr = 4 warps (m32 x n112).
// ===========================================================================
#define FC_ST      40
#define FC_XBUF_B  (64 * FC_ST * 2)        // 5120 B
#define FC_WBUF_B  (224 * FC_ST * 2)       // 17920 B
#define W_IT_B     (32 * FC_ST * 2)        // 2560 B
#define FC_SMEM    (2 * FC_XBUF_B + 2 * FC_WBUF_B + 1024)   // 47104

__global__ __launch_bounds__(128, 2)
void fc_mma_kernel(const float* __restrict__ x, const float* __restrict__ bfc)
{
    extern __shared__ __align__(16) char sm_raw[];
    __half* sxh = (__half*)sm_raw;
    __half* swh = (__half*)(sm_raw + 2 * FC_XBUF_B);
    float* red = (float*)(sm_raw + 2 * FC_XBUF_B + 2 * FC_WBUF_B);

    const int tid = threadIdx.x, lane = tid & 31, warp = tid >> 5;
    const int g = lane >> 2, t = lane & 3;
    const int wm = warp & 1, wn = warp >> 1;
    const int m0 = blockIdx.x * 64;

    const int xrow = tid >> 1, xq = tid & 1;
    const float4* xp = (const float4*)(x + (size_t)(m0 + xrow) * C_DIM);
    char* sxh_dst = (char*)(sxh + xrow * FC_ST + xq * 16);

    const int wrow = tid >> 2, wq = tid & 3;
    const __half* whsrc = g_Wfch + (size_t)wrow * C_DIM + wq * 8;
    const uint wdh = smem_u32(swh + wrow * FC_ST + wq * 8);

    uint ah_addr[2];
#pragma unroll
    for (int i = 0; i < 2; i++) {
        uint ab = (uint)((wm * 32 + i * 16 + (lane & 15)) * FC_ST + (lane >> 4) * 8) * 2;
        ah_addr[i] = smem_u32(sxh) + ab;
    }
    const uint b_base  = (uint)((wn * 112 + ((lane >> 4) & 1) * 8 + (lane & 7)) * FC_ST
                                + ((lane >> 3) & 1) * 8) * 2;
    const uint bh_addr = smem_u32(swh) + b_base;

    float acc[2][14][4];
#pragma unroll
    for (int i = 0; i < 2; i++)
#pragma unroll
        for (int j = 0; j < 14; j++)
#pragma unroll
            for (int q = 0; q < 4; q++) acc[i][j][q] = 0.f;

    float4 xr[4];
#pragma unroll
    for (int i = 0; i < 4; i++) xr[i] = xp[xq * 4 + i];
#pragma unroll
    for (int it = 0; it < 7; it++)
        CP_ASYNC16(wdh + it * W_IT_B, whsrc + (size_t)it * 32 * C_DIM);
    CP_COMMIT();
#pragma unroll
    for (int i = 0; i < 4; i++)
        *(uint2*)(sxh_dst + i * 8) = cvt4h(xr[i]);
    CP_WAIT0();
    __syncthreads();

    for (int step = 0; step < 24; step++) {
        const int buf = step & 1;
        const uint xoff  = (uint)buf * FC_XBUF_B;
        const uint woff  = (uint)buf * FC_WBUF_B;
        const uint nxoff = (uint)(buf ^ 1) * FC_XBUF_B;
        const uint nwoff = (uint)(buf ^ 1) * FC_WBUF_B;

        if (step < 23) {
            const int k4 = (step + 1) * 8 + xq * 4;
#pragma unroll
            for (int i = 0; i < 4; i++) xr[i] = xp[k4 + i];
            const int ke = (step + 1) * 32;
#pragma unroll
            for (int it = 0; it < 7; it++)
                CP_ASYNC16(wdh + nwoff + it * W_IT_B, whsrc + (size_t)it * 32 * C_DIM + ke);
            CP_COMMIT();
        }

#pragma unroll
        for (int c = 0; c < 2; c++) {
            const uint coff = c * 32;
            uint ah[2][4];
#pragma unroll
            for (int i = 0; i < 2; i++)
                LDSM_X4(ah[i][0], ah[i][1], ah[i][2], ah[i][3], ah_addr[i] + xoff + coff);
#pragma unroll
            for (int jp = 0; jp < 7; jp++) {
                uint bh[4];
                LDSM_X4(bh[0], bh[1], bh[2], bh[3], bh_addr + woff + jp * 1280 + coff);
                const int j0 = 2 * jp, j1 = j0 + 1;
#pragma unroll
                for (int i = 0; i < 2; i++) {
                    MMA_F16(acc[i][j0][0], acc[i][j0][1], acc[i][j0][2], acc[i][j0][3],
                            ah[i][0], ah[i][1], ah[i][2], ah[i][3], bh[0], bh[1]);
                    MMA_F16(acc[i][j1][0], acc[i][j1][1], acc[i][j1][2], acc[i][j1][3],
                            ah[i][0], ah[i][1], ah[i][2], ah[i][3], bh[2], bh[3]);
                }
            }
        }

        if (step < 23) {
#pragma unroll
            for (int i = 0; i < 4; i++)
                *(uint2*)(sxh_dst + nxoff + i * 8) = cvt4h(xr[i]);
            CP_WAIT0();
        }
        __syncthreads();
    }

    // ---- epilogue: bias + mask, fused row max / sumexp reduce ----
#pragma unroll
    for (int j = 0; j < 14; j++) {
        int col = wn * 112 + j * 8 + t * 2;
        float b0 = (col < NCLS) ? bfc[col] : 0.f;
        float b1 = (col + 1 < NCLS) ? bfc[col + 1] : 0.f;
#pragma unroll
        for (int i = 0; i < 2; i++) {
            if (col < NCLS) { acc[i][j][0] += b0; acc[i][j][2] += b0; }
            else            { acc[i][j][0] = acc[i][j][2] = -1e30f; }
            if (col + 1 < NCLS) { acc[i][j][1] += b1; acc[i][j][3] += b1; }
            else                { acc[i][j][1] = acc[i][j][3] = -1e30f; }
        }
    }
#pragma unroll
    for (int i = 0; i < 2; i++) {
        const int r0 = wm * 32 + i * 16 + g, r1 = r0 + 8;
        float mx0 = -1e30f, mx1 = -1e30f;
#pragma unroll
        for (int j = 0; j < 14; j++) {
            mx0 = fmaxf(mx0, fmaxf(acc[i][j][0], acc[i][j][1]));
            mx1 = fmaxf(mx1, fmaxf(acc[i][j][2], acc[i][j][3]));
        }
#pragma unroll
        for (int off = 1; off <= 2; off <<= 1) {
            mx0 = fmaxf(mx0, __shfl_xor_sync(0xffffffffu, mx0, off));
            mx1 = fmaxf(mx1, __shfl_xor_sync(0xffffffffu, mx1, off));
        }
        if (t == 0) { red[wn * 64 + r0] = mx0; red[wn * 64 + r1] = mx1; }
    }
    __syncthreads();
#pragma unroll
    for (int i = 0; i < 2; i++) {
        const int r0 = wm * 32 + i * 16 + g, r1 = r0 + 8;
        const float rm0 = fmaxf(red[r0], red[64 + r0]);
        const float rm1 = fmaxf(red[r1], red[64 + r1]);
        float s0 = 0.f, s1 = 0.f;
#pragma unroll
        for (int j = 0; j < 14; j++) {
            s0 += expf(acc[i][j][0] - rm0) + expf(acc[i][j][1] - rm0);
            s1 += expf(acc[i][j][2] - rm1) + expf(acc[i][j][3] - rm1);
        }
#pragma unroll
        for (int off = 1; off <= 2; off <<= 1) {
            s0 += __shfl_xor_sync(0xffffffffu, s0, off);
            s1 += __shfl_xor_sync(0xffffffffu, s1, off);
        }
        if (t == 0) { red[128 + wn * 64 + r0] = s0; red[128 + wn * 64 + r1] = s1; }
    }
    __syncthreads();
    if (wn == 0 && t == 0) {
#pragma unroll
        for (int i = 0; i < 2; i++) {
            const int r0 = wm * 32 + i * 16 + g, r1 = r0 + 8;
            g_maxprob[m0 + r0] = 1.f / (red[128 + r0] + red[128 + 64 + r0]);
            g_maxprob[m0 + r1] = 1.f / (red[128 + r1] + red[128 + 64 + r1]);
        }
    }
}

// ===========================================================================
// Kernel 2: part_logits (8x8 mean-pool, stride 3, pad 2) * mask -> argmax
// ===========================================================================
__global__ void sel_kernel(const float* __restrict__ mask)
{
    int b = blockIdx.x;
    __shared__ float map[784];
    __shared__ float vals[81];
    int p = threadIdx.x;
    for (int i = p; i < 784; i += 128) map[i] = g_maxprob[b * 784 + i];
    __syncthreads();
    if (p < 81) {
        int oy = p / 9, ox = p % 9;
        float s = 0.f;
#pragma unroll
        for (int i = 0; i < 8; i++) {
            int h = oy * 3 - 2 + i;
            if (h < 0 || h >= 28) continue;
#pragma unroll
            for (int j = 0; j < 8; j++) {
                int w = ox * 3 - 2 + j;
                if (w < 0 || w >= 28) continue;
                s += map[h * 28 + w];
            }
        }
        vals[p] = mask[b * 81 + p] * (s * (1.f / 64.f));
    }
    __syncthreads();
    if (p == 0) {
        float best = vals[0];
        int bi = 0;
        for (int q = 1; q < 81; q++)
            if (vals[q] > best) { best = vals[q]; bi = q; }
        g_sel[b] = bi;
    }
}

// ===========================================================================
// Kernel 3: gather selected patches -> fp16 A matrices (x4 vectorized)
// ===========================================================================
__global__ void gather_kernel(const float* __restrict__ x)
{
    int p    = blockIdx.x;
    int b    = blockIdx.y;
    int part = blockIdx.z;
    int sel  = __ldg(&g_sel[b]);
    int oy = sel / 9, ox = sel % 9;
    int i = p >> 3, j = p & 7;
    int c = threadIdx.x * 4;

    const float* xb = x + (size_t)b * 784 * C_DIM;
    __half* oh = &g_Ah[part][(size_t)(b * 64 + p) * C_DIM + c];

    float4 v;
    if (part == 0) {
        int h = oy * 3 - 2 + i, w = ox * 3 - 2 + j;
        bool ok = (h >= 0 && h < 28 && w >= 0 && w < 28);
        v = ok ? *(const float4*)&xb[(size_t)(h * 28 + w) * C_DIM + c]
               : make_float4(0.f, 0.f, 0.f, 0.f);
    } else {
        int   n, basepad;
        float scale, offs;
        if (part == 1) { n = 6; basepad = 1; scale = 0.75f; offs = -0.125f; }
        else           { n = 4; basepad = 0; scale = 0.5f;  offs = -0.25f;  }
        float sy = fminf(fmaxf(scale * i + offs, 0.f), (float)(n - 1));
        float sx = fminf(fmaxf(scale * j + offs, 0.f), (float)(n - 1));
        int iy0 = (int)sy; float fy = sy - iy0; int iy1 = min(iy0 + 1, n - 1);
        int ix0 = (int)sx; float fx = sx - ix0; int ix1 = min(ix0 + 1, n - 1);
        int hb = oy * 3 - basepad, wb = ox * 3 - basepad;
        int h0 = hb + iy0, h1 = hb + iy1, w0 = wb + ix0, w1 = wb + ix1;
        bool okh0 = (h0 >= 0 && h0 < 28), okh1 = (h1 >= 0 && h1 < 28);
        bool okw0 = (w0 >= 0 && w0 < 28), okw1 = (w1 >= 0 && w1 < 28);
        bool ok00 = okh0 && okw0, ok01 = okh0 && okw1;
        bool ok10 = okh1 && okw0, ok11 = okh1 && okw1;
        const float4 z = make_float4(0.f, 0.f, 0.f, 0.f);
        float4 v00 = ok00 ? *(const float4*)&xb[(size_t)(h0 * 28 + w0) * C_DIM + c] : z;
        float4 v01 = ok01 ? *(const float4*)&xb[(size_t)(h0 * 28 + w1) * C_DIM + c] : z;
        float4 v10 = ok10 ? *(const float4*)&xb[(size_t)(h1 * 28 + w0) * C_DIM + c] : z;
        float4 v11 = ok11 ? *(const float4*)&xb[(size_t)(h1 * 28 + w1) * C_DIM + c] : z;
        float gy = 1.f - fy, gx = 1.f - fx;
        v.x = gy * (gx * v00.x + fx * v01.x) + fy * (gx * v10.x + fx * v11.x);
        v.y = gy * (gx * v00.y + fx * v01.y) + fy * (gx * v10.y + fx * v11.y);
        v.z = gy * (gx * v00.z + fx * v01.z) + fy * (gx * v10.z + fx * v11.z);
        v.w = gy * (gx * v00.w + fx * v01.w) + fy * (gx * v10.w + fx * v11.w);
    }
    *(uint2*)oh = cvt4h(v);
}

// ===========================================================================
// Kernel 4: parts GEMM (plain fp16 HMMA). BM=64, BN=64, BK=32, grid(16,12).
// ===========================================================================
#define P_ST    40
#define P_BUF   (64 * P_ST)
#define P_BUF_B (P_BUF * 2)

__global__ __launch_bounds__(256, 3)
void parts_mma_kernel(float* __restrict__ out)
{
    __shared__ __align__(16) __half sah[2][P_BUF];
    __shared__ __align__(16) __half swh[2][P_BUF];

    const int tid = threadIdx.x, lane = tid & 31, warp = tid >> 5;
    const int g = lane >> 2, t = lane & 3;
    const int wm = warp & 3, wn = warp >> 2;
    const int m0 = blockIdx.x * 64;
    const int n0c = blockIdx.y * 64;
    const int part = (n0c < 192) ? 0 : (n0c < 384) ? 1 : 2;

    // fill: 2 chunks per thread (A, W); row = tid>>2, q = tid&3
    const int frow = tid >> 2, fq = tid & 3;
    const __half* ahsrc = g_Ah[part] + (size_t)(m0 + frow) * C_DIM + fq * 8;
    const __half* whsrc = g_Wph + (size_t)(n0c + frow) * C_DIM + fq * 8;
    const uint ahdst = smem_u32(sah[0] + frow * P_ST + fq * 8);
    const uint whdst = smem_u32(swh[0] + frow * P_ST + fq * 8);

    const uint a_base  = (uint)((wm * 16 + (lane & 15)) * P_ST + (lane >> 4) * 8) * 2;
    const uint ah_addr = smem_u32(sah[0]) + a_base;
    const uint b_base  = (uint)((wn * 32 + ((lane >> 4) & 1) * 8 + (lane & 7)) * P_ST
                                + ((lane >> 3) & 1) * 8) * 2;
    const uint bh_addr = smem_u32(swh[0]) + b_base;

    float acc[4][4];
#pragma unroll
    for (int j = 0; j < 4; j++)
#pragma unroll
        for (int q = 0; q < 4; q++) acc[j][q] = 0.f;

    CP_ASYNC16(ahdst, ahsrc);
    CP_ASYNC16(whdst, whsrc);
    CP_COMMIT();
    CP_WAIT0();
    __syncthreads();

    for (int step = 0; step < 24; step++) {
        const int buf = step & 1;
        const uint off  = (uint)buf * P_BUF_B;
        const uint noff = (uint)(buf ^ 1) * P_BUF_B;

        if (step < 23) {
            CP_ASYNC16(ahdst + noff, ahsrc + (step + 1) * 32);
            CP_ASYNC16(whdst + noff, whsrc + (step + 1) * 32);
            CP_COMMIT();
        }

#pragma unroll
        for (int c = 0; c < 2; c++) {
            const uint coff = c * 32;
            uint ah[4];
            LDSM_X4(ah[0], ah[1], ah[2], ah[3], ah_addr + off + coff);
#pragma unroll
            for (int jp = 0; jp < 2; jp++) {
                uint bh[4];
                LDSM_X4(bh[0], bh[1], bh[2], bh[3], bh_addr + off + jp * 1280 + coff);
                const int j0 = 2 * jp, j1 = j0 + 1;
                MMA_F16(acc[j0][0], acc[j0][1], acc[j0][2], acc[j0][3],
                        ah[0], ah[1], ah[2], ah[3], bh[0], bh[1]);
                MMA_F16(acc[j1][0], acc[j1][1], acc[j1][2], acc[j1][3],
                        ah[0], ah[1], ah[2], ah[3], bh[2], bh[3]);
            }
        }

        if (step < 23) CP_WAIT0();
        __syncthreads();
    }

#pragma unroll
    for (int j = 0; j < 4; j++) {
        int col = n0c + wn * 32 + j * 8 + t * 2;
        int m   = m0 + wm * 16 + g;
        float2 bc = *(float2*)&g_bias[col];
        *(float2*)&out[(size_t)m * 768 + col] =
            make_float2(acc[j][0] + bc.x, acc[j][1] + bc.y);
        *(float2*)&out[(size_t)(m + 8) * 768 + col] =
            make_float2(acc[j][2] + bc.x, acc[j][3] + bc.y);
    }
}

// ===========================================================================
// Kernel 5: image patch gather + bilinear 224.  grid (48, 28), 224 thr.
// ===========================================================================
__global__ void image_kernel(const float* __restrict__ img, float* __restrict__ out)
{
    int bc = blockIdx.x;
    int b  = bc / 3;
    int ox = threadIdx.x;

    int sel = __ldg(&g_sel[b]);
    int r0 = (sel / 9) * 48 - 32;
    int c0 = (sel % 9) * 48 - 32;

    const float s = 128.f / 224.f;
    float sx = fminf(fmaxf((ox + 0.5f) * s - 0.5f, 0.f), 127.f);
    int px0 = (int)sx; float fx = sx - px0; int px1 = min(px0 + 1, 127);
    int gx0 = c0 + px0, gx1 = c0 + px1;
    bool okx0 = (gx0 >= 0 && gx0 < 448), okx1 = (gx1 >= 0 && gx1 < 448);

    const float* ib = img + (size_t)bc * 448 * 448;
    float* ob = out + (size_t)bc * 224 * 224;

#pragma unroll
    for (int oy8 = 0; oy8 < 8; oy8++) {
        int oy = blockIdx.y * 8 + oy8;
        float sy = fminf(fmaxf((oy + 0.5f) * s - 0.5f, 0.f), 127.f);
        int py0 = (int)sy; float fy = sy - py0; int py1 = min(py0 + 1, 127);
        int gy0 = r0 + py0, gy1 = r0 + py1;
        bool oky0 = (gy0 >= 0 && gy0 < 448), oky1 = (gy1 >= 0 && gy1 < 448);
        float v00 = (oky0 && okx0) ? ib[gy0 * 448 + gx0] : 0.f;
        float v01 = (oky0 && okx1) ? ib[gy0 * 448 + gx1] : 0.f;
        float v10 = (oky1 && okx0) ? ib[gy1 * 448 + gx0] : 0.f;
        float v11 = (oky1 && okx1) ? ib[gy1 * 448 + gx1] : 0.f;
        ob[oy * 224 + ox] = (1.f - fy) * ((1.f - fx) * v00 + fx * v01)
                          +        fy  * ((1.f - fx) * v10 + fx * v11);
    }
}

// ===========================================================================
extern "C" void kernel_launch(void* const* d_in, const int* in_sizes, int n_in,
                              void* d_out, int out_size)
{
    const float* x    = (const float*)d_in[0];
    const float* mask = (const float*)d_in[1];
    const float* img  = (const float*)d_in[2];
    const float* Wfc  = (const float*)d_in[3];
    const float* bfc  = (const float*)d_in[4];
    const float* Wl   = (const float*)d_in[5];
    const float* bl   = (const float*)d_in[6];
    const float* Wm   = (const float*)d_in[7];
    const float* bm   = (const float*)d_in[8];
    const float* Ws   = (const float*)d_in[9];
    const float* bsv  = (const float*)d_in[10];

    float* out_ff  = (float*)d_out;
    float* out_img = (float*)d_out + FF_ELEMS;

    conv_w_kernel<<<(FC4 + P4 + 255) / 256, 256>>>(Wfc, Wl, Wm, Ws, bl, bm, bsv);

    cudaFuncSetAttribute(fc_mma_kernel,
                         cudaFuncAttributeMaxDynamicSharedMemorySize, FC_SMEM);
    fc_mma_kernel<<<M_ROWS / 64, 128, FC_SMEM>>>(x, bfc);

    sel_kernel<<<BATCH, 128>>>(mask);
    {
        dim3 g(64, BATCH, 3);
        gather_kernel<<<g, 192>>>(x);
    }
    {
        dim3 g(16, 12);
        parts_mma_kernel<<<g, 256>>>(out_ff);
    }
    {
        dim3 g(48, 28);
        image_kernel<<<g, 224>>>(img, out_img);
    }
}